// round 8
// baseline (speedup 1.0000x reference)
#include <cuda_runtime.h>

#define HH 128
#define WW 128
#define HWSZ (HH * WW)

// ---------------- scratch (static device arrays; no allocation) ----------------
__device__ float  g_h1[2 * 64 * HWSZ];          // conv1 out
__device__ float  g_h2[2 * 64 * HWSZ];          // conv2 out
__device__ float  g_o [2 * 432 * HWSZ];         // conv3 out (raw offsets/mask logits)
__device__ float4 g_xt[2 * 16 * HWSZ];          // x transposed to [B,G,H,W,cg=4]

// ---------------- conv 3x3, pad 1, stride 1, NCHW fp32 (scalar FFMA) ----------------
// tile 64 wide x 32 tall, 256 threads (tx 0..31, ty 0..7), each thread computes
// 2 wide x 4 tall pixels for OCB=8 output channels. Input staged CCHUNK=4 at a time.
constexpr int OCB = 8;
constexpr int CCHUNK = 4;
constexpr int TW = 64;   // tile width
constexpr int TH = 32;   // tile height

template <bool LEAKY>
__global__ __launch_bounds__(256, 2)
void conv3x3_kernel(const float* __restrict__ in, const float* __restrict__ wgt,
                    const float* __restrict__ bias, float* __restrict__ out,
                    int Cin, int Cout) {
    __shared__ float s_in[CCHUNK][TH + 2][TW + 2];   // 4 x 34 x 66
    __shared__ float s_w[CCHUNK][OCB][9];

    const int tid = threadIdx.x;
    const int tx = tid & 31;
    const int ty = tid >> 5;
    const int tile_id = blockIdx.x;                  // 8 tiles: 2 wide x 4 tall
    const int x0 = (tile_id & 1) * TW;
    const int y0 = (tile_id >> 1) * TH;
    const int ocb = blockIdx.y;
    const int b = blockIdx.z;

    const float* in_b = in + (size_t)b * Cin * HWSZ;

    float acc[OCB][4][2];
#pragma unroll
    for (int oc = 0; oc < OCB; oc++)
#pragma unroll
        for (int r = 0; r < 4; r++) { acc[oc][r][0] = 0.f; acc[oc][r][1] = 0.f; }

    const int s_ch = tid >> 6;        // 0..3: channel this thread stages
    const int s_ln = tid & 63;        // lane within channel (0..63)

    for (int c0 = 0; c0 < Cin; c0 += CCHUNK) {
        __syncthreads();
        // ---- stage input chunk (zero halo) ----
        {
            const float* src = in_b + (size_t)(c0 + s_ch) * HWSZ;
#pragma unroll 2
            for (int r = 0; r < TH + 2; r++) {
                int gy = y0 - 1 + r;
                bool yok = ((unsigned)gy < HH);
                const float* row = src + gy * WW;
                {
                    int gx = x0 - 1 + s_ln;
                    float v = 0.f;
                    if (yok && (unsigned)gx < WW) v = row[gx];
                    s_in[s_ch][r][s_ln] = v;
                }
                if (s_ln < 2) {
                    int gx = x0 - 1 + 64 + s_ln;
                    float v = 0.f;
                    if (yok && (unsigned)gx < WW) v = row[gx];
                    s_in[s_ch][r][64 + s_ln] = v;
                }
            }
        }
        // ---- stage weights: [ci][oc][9] (288 entries > 256 threads: strided loop!) ----
        for (int idx = tid; idx < CCHUNK * OCB * 9; idx += 256) {
            int ci = idx / (OCB * 9);
            int rem = idx - ci * (OCB * 9);
            int oc = rem / 9;
            int k = rem - oc * 9;
            s_w[ci][oc][k] = wgt[(size_t)((ocb * OCB + oc) * Cin + c0 + ci) * 9 + k];
        }
        __syncthreads();

#pragma unroll
        for (int ci = 0; ci < CCHUNK; ci++) {
            float iv[6][4];
#pragma unroll
            for (int r = 0; r < 6; r++) {
                float2 a = *(const float2*)&s_in[ci][4 * ty + r][2 * tx];
                float2 c = *(const float2*)&s_in[ci][4 * ty + r][2 * tx + 2];
                iv[r][0] = a.x; iv[r][1] = a.y; iv[r][2] = c.x; iv[r][3] = c.y;
            }
#pragma unroll
            for (int oc = 0; oc < OCB; oc++) {
#pragma unroll
                for (int ky = 0; ky < 3; ky++) {
#pragma unroll
                    for (int kx = 0; kx < 3; kx++) {
                        float w = s_w[ci][oc][ky * 3 + kx];
                        acc[oc][0][0] = fmaf(iv[ky][kx],     w, acc[oc][0][0]);
                        acc[oc][0][1] = fmaf(iv[ky][kx + 1], w, acc[oc][0][1]);
                        acc[oc][1][0] = fmaf(iv[ky + 1][kx],     w, acc[oc][1][0]);
                        acc[oc][1][1] = fmaf(iv[ky + 1][kx + 1], w, acc[oc][1][1]);
                        acc[oc][2][0] = fmaf(iv[ky + 2][kx],     w, acc[oc][2][0]);
                        acc[oc][2][1] = fmaf(iv[ky + 2][kx + 1], w, acc[oc][2][1]);
                        acc[oc][3][0] = fmaf(iv[ky + 3][kx],     w, acc[oc][3][0]);
                        acc[oc][3][1] = fmaf(iv[ky + 3][kx + 1], w, acc[oc][3][1]);
                    }
                }
            }
        }
    }

    const int oy = y0 + 4 * ty;
    const int ox = x0 + 2 * tx;
#pragma unroll
    for (int oc = 0; oc < OCB; oc++) {
        float bv = bias[ocb * OCB + oc];
        float* op = out + ((size_t)b * Cout + ocb * OCB + oc) * HWSZ;
#pragma unroll
        for (int r = 0; r < 4; r++) {
            float2 v;
            v.x = acc[oc][r][0] + bv;
            v.y = acc[oc][r][1] + bv;
            if (LEAKY) {
                v.x = (v.x >= 0.f) ? v.x : 0.1f * v.x;
                v.y = (v.y >= 0.f) ? v.y : 0.1f * v.y;
            }
            *(float2*)&op[(oy + r) * WW + ox] = v;
        }
    }
}

// ---------------- x transpose: [B,64,H,W] -> [B,16,H,W,4] ----------------
__global__ void transpose_x_kernel(const float* __restrict__ x, float4* __restrict__ xt) {
    int idx = blockIdx.x * 256 + threadIdx.x;
    if (idx >= 2 * 16 * HWSZ) return;
    int p = idx & (HWSZ - 1);
    int bg = idx / HWSZ;
    const float* src = x + (size_t)bg * 4 * HWSZ + p;
    float4 v;
    v.x = src[0];
    v.y = src[HWSZ];
    v.z = src[2 * HWSZ];
    v.w = src[3 * HWSZ];
    xt[idx] = v;
}

// ---------------- deformable gather + per-pixel [64 x 576] contraction --------------
__global__ __launch_bounds__(128, 3)
void deform_kernel(const float4* __restrict__ xt,     // [B,16,HW] float4
                   const float* __restrict__ o,       // [B,432,HW]
                   const float* __restrict__ flow,    // [B,2,HW]
                   const float* __restrict__ weight,  // [64,64,9]
                   float* __restrict__ out) {         // [B,64,HW]
    __shared__ __align__(16) float s_w[64 * 36];

    const int tid = threadIdx.x;
    const int b = blockIdx.y;
    const int p = blockIdx.x * 128 + tid;
    const int h = p >> 7;
    const int w = p & 127;

    const float* ob = o + (size_t)b * 432 * HWSZ + p;
    const float fy = flow[((size_t)b * 2 + 1) * HWSZ + p];
    const float fx = flow[((size_t)b * 2 + 0) * HWSZ + p];

    float acc[64];
#pragma unroll
    for (int i = 0; i < 64; i++) acc[i] = 0.f;

    for (int g = 0; g < 16; g++) {
        __syncthreads();
        for (int idx = tid; idx < 64 * 36; idx += 128) {
            int oo = idx / 36;
            int m = idx - oo * 36;
            s_w[idx] = weight[(size_t)oo * 576 + g * 36 + m];
        }
        __syncthreads();

        const float4* xg = xt + (size_t)(b * 16 + g) * HWSZ;
        float val[36];

#pragma unroll
        for (int k = 0; k < 9; k++) {
            float lo_y = ob[(size_t)(g * 18 + 2 * k) * HWSZ];
            float lo_x = ob[(size_t)(g * 18 + 2 * k + 1) * HWSZ];
            float lo_m = ob[(size_t)(288 + g * 9 + k) * HWSZ];

            float offy = 10.f * tanhf(lo_y) + fy;
            float offx = 10.f * tanhf(lo_x) + fx;
            float msk = 1.f / (1.f + expf(-lo_m));

            float py = (float)(h + (k / 3) - 1) + offy;
            float px = (float)(w + (k % 3) - 1) + offx;

            float y0f = floorf(py);
            float x0f = floorf(px);
            float wy = py - y0f;
            float wx = px - x0f;
            int y0 = (int)y0f;
            int x0 = (int)x0f;

            bool y0v = ((unsigned)y0 < HH);
            bool y1v = ((unsigned)(y0 + 1) < HH);
            bool x0v = ((unsigned)x0 < WW);
            bool x1v = ((unsigned)(x0 + 1) < WW);

            float4 v00 = make_float4(0.f, 0.f, 0.f, 0.f);
            float4 v01 = v00, v10 = v00, v11 = v00;
            if (y0v && x0v) v00 = __ldg(&xg[y0 * WW + x0]);
            if (y0v && x1v) v01 = __ldg(&xg[y0 * WW + x0 + 1]);
            if (y1v && x0v) v10 = __ldg(&xg[(y0 + 1) * WW + x0]);
            if (y1v && x1v) v11 = __ldg(&xg[(y0 + 1) * WW + x0 + 1]);

            float w00 = (1.f - wy) * (1.f - wx);
            float w01 = (1.f - wy) * wx;
            float w10 = wy * (1.f - wx);
            float w11 = wy * wx;

            val[0 * 9 + k] = msk * (w00 * v00.x + w01 * v01.x + w10 * v10.x + w11 * v11.x);
            val[1 * 9 + k] = msk * (w00 * v00.y + w01 * v01.y + w10 * v10.y + w11 * v11.y);
            val[2 * 9 + k] = msk * (w00 * v00.z + w01 * v01.z + w10 * v10.z + w11 * v11.z);
            val[3 * 9 + k] = msk * (w00 * v00.w + w01 * v01.w + w10 * v10.w + w11 * v11.w);
        }

        const float4* sw4 = (const float4*)s_w;
#pragma unroll
        for (int oo = 0; oo < 64; oo++) {
#pragma unroll
            for (int m4 = 0; m4 < 9; m4++) {
                float4 w4 = sw4[oo * 9 + m4];
                acc[oo] = fmaf(val[m4 * 4 + 0], w4.x, acc[oo]);
                acc[oo] = fmaf(val[m4 * 4 + 1], w4.y, acc[oo]);
                acc[oo] = fmaf(val[m4 * 4 + 2], w4.z, acc[oo]);
                acc[oo] = fmaf(val[m4 * 4 + 3], w4.w, acc[oo]);
            }
        }
    }

#pragma unroll
    for (int oo = 0; oo < 64; oo++)
        out[((size_t)b * 64 + oo) * HWSZ + p] = acc[oo];
}

// ---------------- launch ----------------
extern "C" void kernel_launch(void* const* d_in, const int* in_sizes, int n_in,
                              void* d_out, int out_size) {
    const float* x          = (const float*)d_in[0];
    const float* extra_feat = (const float*)d_in[1];
    const float* flow       = (const float*)d_in[2];
    const float* w1         = (const float*)d_in[3];
    const float* b1         = (const float*)d_in[4];
    const float* w2         = (const float*)d_in[5];
    const float* b2         = (const float*)d_in[6];
    const float* w3         = (const float*)d_in[7];
    const float* b3         = (const float*)d_in[8];
    const float* weight     = (const float*)d_in[9];
    float* out = (float*)d_out;

    float *h1, *h2, *obuf;
    float4* xt;
    cudaGetSymbolAddress((void**)&h1, g_h1);
    cudaGetSymbolAddress((void**)&h2, g_h2);
    cudaGetSymbolAddress((void**)&obuf, g_o);
    cudaGetSymbolAddress((void**)&xt, g_xt);

    transpose_x_kernel<<<(2 * 16 * HWSZ + 255) / 256, 256>>>(x, xt);

    // conv1: 128 -> 64, leaky
    conv3x3_kernel<true><<<dim3(8, 64 / OCB, 2), 256>>>(extra_feat, w1, b1, h1, 128, 64);
    // conv2: 64 -> 64, leaky
    conv3x3_kernel<true><<<dim3(8, 64 / OCB, 2), 256>>>(h1, w2, b2, h2, 64, 64);
    // conv3: 64 -> 432, linear
    conv3x3_kernel<false><<<dim3(8, 432 / OCB, 2), 256>>>(h2, w3, b3, obuf, 64, 432);

    // deformable gather + contraction
    deform_kernel<<<dim3(HWSZ / 128, 2), 128>>>(xt, obuf, flow, weight, out);
}

// round 9
// speedup vs baseline: 1.6017x; 1.6017x over previous
#include <cuda_runtime.h>

#define HH 128
#define WW 128
#define HWSZ (HH * WW)

// ---------------- scratch (static device arrays; no allocation) ----------------
__device__ float  g_h1[2 * 64 * HWSZ];          // conv1 out
__device__ float  g_h2[2 * 64 * HWSZ];          // conv2 out
__device__ float  g_o [2 * 432 * HWSZ];         // conv3 out (raw offsets/mask logits)
__device__ float4 g_xt[2 * 16 * HWSZ];          // x transposed to [B,G,H,W,cg=4]

// ---------------- conv 3x3, pad 1, stride 1, NCHW fp32 ----------------
// R1-proven shape: tile 32x32, 256 threads (16x16), 2x2 px/thread, OCB=8, CCHUNK=8.
// Change vs R1: weights stored padded [oc][ci][12] and read as 3x LDS.128 per oc.
constexpr int TILE = 32;
constexpr int OCB = 8;
constexpr int CCHUNK = 8;

template <bool LEAKY>
__global__ __launch_bounds__(256, 2)
void conv3x3_kernel(const float* __restrict__ in, const float* __restrict__ wgt,
                    const float* __restrict__ bias, float* __restrict__ out,
                    int Cin, int Cout) {
    __shared__ float s_in[CCHUNK][34][36];                 // padded rows
    __shared__ __align__(16) float s_w[OCB][CCHUNK][12];   // 9 used, padded to 12 for LDS.128

    const int tx = threadIdx.x & 15;
    const int ty = threadIdx.x >> 4;
    const int tile_id = blockIdx.x;                  // 16 tiles (4x4)
    const int ty0 = (tile_id / (WW / TILE)) * TILE;
    const int tx0 = (tile_id % (WW / TILE)) * TILE;
    const int ocb = blockIdx.y;
    const int b = blockIdx.z;

    const float* in_b = in + (size_t)b * Cin * HWSZ;

    float acc[OCB][4];
#pragma unroll
    for (int i = 0; i < OCB; i++) {
        acc[i][0] = 0.f; acc[i][1] = 0.f; acc[i][2] = 0.f; acc[i][3] = 0.f;
    }

    for (int c0 = 0; c0 < Cin; c0 += CCHUNK) {
        __syncthreads();
        // stage input chunk: CCHUNK x 34 x 34 (with zero halo)  [R1-exact]
        for (int idx = threadIdx.x; idx < CCHUNK * 34 * 34; idx += 256) {
            int ch = idx / (34 * 34);
            int rem = idx % (34 * 34);
            int r = rem / 34;
            int cc = rem % 34;
            int gy = ty0 - 1 + r;
            int gx = tx0 - 1 + cc;
            float v = 0.f;
            if (gy >= 0 && gy < HH && gx >= 0 && gx < WW)
                v = in_b[(size_t)(c0 + ch) * HWSZ + gy * WW + gx];
            s_in[ch][r][cc] = v;
        }
        // stage weights: OCB x CCHUNK x 9 (into 12-padded rows)
        for (int idx = threadIdx.x; idx < OCB * CCHUNK * 9; idx += 256) {
            int oc = idx / (CCHUNK * 9);
            int rem = idx % (CCHUNK * 9);
            int ci = rem / 9;
            int k = rem % 9;
            s_w[oc][ci][k] = wgt[(size_t)((ocb * OCB + oc) * Cin + c0 + ci) * 9 + k];
        }
        __syncthreads();

#pragma unroll
        for (int ci = 0; ci < CCHUNK; ci++) {
            float iv[4][4];
#pragma unroll
            for (int dy = 0; dy < 4; dy++)
#pragma unroll
                for (int dx = 0; dx < 4; dx++)
                    iv[dy][dx] = s_in[ci][2 * ty + dy][2 * tx + dx];
#pragma unroll
            for (int oc = 0; oc < OCB; oc++) {
                // 9 weights via 3x LDS.128 (broadcast, conflict-free)
                const float4* wv = (const float4*)s_w[oc][ci];
                float4 wa = wv[0];
                float4 wb = wv[1];
                float4 wc = wv[2];
                float wk[9] = { wa.x, wa.y, wa.z, wa.w,
                                wb.x, wb.y, wb.z, wb.w,
                                wc.x };
#pragma unroll
                for (int ky = 0; ky < 3; ky++)
#pragma unroll
                    for (int kx = 0; kx < 3; kx++) {
                        float w = wk[ky * 3 + kx];
                        acc[oc][0] = fmaf(iv[ky][kx],         w, acc[oc][0]);
                        acc[oc][1] = fmaf(iv[ky][kx + 1],     w, acc[oc][1]);
                        acc[oc][2] = fmaf(iv[ky + 1][kx],     w, acc[oc][2]);
                        acc[oc][3] = fmaf(iv[ky + 1][kx + 1], w, acc[oc][3]);
                    }
            }
        }
    }

    const int oy = ty0 + 2 * ty;
    const int ox = tx0 + 2 * tx;
#pragma unroll
    for (int oc = 0; oc < OCB; oc++) {
        float bv = bias[ocb * OCB + oc];
        float* op = out + ((size_t)b * Cout + ocb * OCB + oc) * HWSZ;
#pragma unroll
        for (int q = 0; q < 4; q++) {
            float v = acc[oc][q] + bv;
            if (LEAKY) v = (v >= 0.f) ? v : 0.1f * v;
            int yy = oy + (q >> 1);
            int xx = ox + (q & 1);
            op[yy * WW + xx] = v;
        }
    }
}

// ---------------- x transpose: [B,64,H,W] -> [B,16,H,W,4] ----------------
__global__ void transpose_x_kernel(const float* __restrict__ x, float4* __restrict__ xt) {
    int idx = blockIdx.x * 256 + threadIdx.x;
    if (idx >= 2 * 16 * HWSZ) return;
    int p = idx & (HWSZ - 1);
    int bg = idx / HWSZ;
    const float* src = x + (size_t)bg * 4 * HWSZ + p;
    float4 v;
    v.x = src[0];
    v.y = src[HWSZ];
    v.z = src[2 * HWSZ];
    v.w = src[3 * HWSZ];
    xt[idx] = v;
}

// ---------------- deformable gather + per-pixel [64 x 576] contraction [R1-exact] ----
__global__ __launch_bounds__(128, 3)
void deform_kernel(const float4* __restrict__ xt,     // [B,16,HW] float4
                   const float* __restrict__ o,       // [B,432,HW]
                   const float* __restrict__ flow,    // [B,2,HW]
                   const float* __restrict__ weight,  // [64,64,9]
                   float* __restrict__ out) {         // [B,64,HW]
    __shared__ __align__(16) float s_w[64 * 36];

    const int tid = threadIdx.x;
    const int b = blockIdx.y;
    const int p = blockIdx.x * 128 + tid;
    const int h = p >> 7;
    const int w = p & 127;

    const float* ob = o + (size_t)b * 432 * HWSZ + p;
    const float fy = flow[((size_t)b * 2 + 1) * HWSZ + p];
    const float fx = flow[((size_t)b * 2 + 0) * HWSZ + p];

    float acc[64];
#pragma unroll
    for (int i = 0; i < 64; i++) acc[i] = 0.f;

    for (int g = 0; g < 16; g++) {
        __syncthreads();
        for (int idx = tid; idx < 64 * 36; idx += 128) {
            int oo = idx / 36;
            int m = idx - oo * 36;
            s_w[idx] = weight[(size_t)oo * 576 + g * 36 + m];
        }
        __syncthreads();

        const float4* xg = xt + (size_t)(b * 16 + g) * HWSZ;
        float val[36];

#pragma unroll
        for (int k = 0; k < 9; k++) {
            float lo_y = ob[(size_t)(g * 18 + 2 * k) * HWSZ];
            float lo_x = ob[(size_t)(g * 18 + 2 * k + 1) * HWSZ];
            float lo_m = ob[(size_t)(288 + g * 9 + k) * HWSZ];

            float offy = 10.f * tanhf(lo_y) + fy;
            float offx = 10.f * tanhf(lo_x) + fx;
            float msk = 1.f / (1.f + expf(-lo_m));

            float py = (float)(h + (k / 3) - 1) + offy;
            float px = (float)(w + (k % 3) - 1) + offx;

            float y0f = floorf(py);
            float x0f = floorf(px);
            float wy = py - y0f;
            float wx = px - x0f;
            int y0 = (int)y0f;
            int x0 = (int)x0f;

            bool y0v = ((unsigned)y0 < HH);
            bool y1v = ((unsigned)(y0 + 1) < HH);
            bool x0v = ((unsigned)x0 < WW);
            bool x1v = ((unsigned)(x0 + 1) < WW);

            float4 v00 = make_float4(0.f, 0.f, 0.f, 0.f);
            float4 v01 = v00, v10 = v00, v11 = v00;
            if (y0v && x0v) v00 = __ldg(&xg[y0 * WW + x0]);
            if (y0v && x1v) v01 = __ldg(&xg[y0 * WW + x0 + 1]);
            if (y1v && x0v) v10 = __ldg(&xg[(y0 + 1) * WW + x0]);
            if (y1v && x1v) v11 = __ldg(&xg[(y0 + 1) * WW + x0 + 1]);

            float w00 = (1.f - wy) * (1.f - wx);
            float w01 = (1.f - wy) * wx;
            float w10 = wy * (1.f - wx);
            float w11 = wy * wx;

            val[0 * 9 + k] = msk * (w00 * v00.x + w01 * v01.x + w10 * v10.x + w11 * v11.x);
            val[1 * 9 + k] = msk * (w00 * v00.y + w01 * v01.y + w10 * v10.y + w11 * v11.y);
            val[2 * 9 + k] = msk * (w00 * v00.z + w01 * v01.z + w10 * v10.z + w11 * v11.z);
            val[3 * 9 + k] = msk * (w00 * v00.w + w01 * v01.w + w10 * v10.w + w11 * v11.w);
        }

        const float4* sw4 = (const float4*)s_w;
#pragma unroll
        for (int oo = 0; oo < 64; oo++) {
#pragma unroll
            for (int m4 = 0; m4 < 9; m4++) {
                float4 w4 = sw4[oo * 9 + m4];
                acc[oo] = fmaf(val[m4 * 4 + 0], w4.x, acc[oo]);
                acc[oo] = fmaf(val[m4 * 4 + 1], w4.y, acc[oo]);
                acc[oo] = fmaf(val[m4 * 4 + 2], w4.z, acc[oo]);
                acc[oo] = fmaf(val[m4 * 4 + 3], w4.w, acc[oo]);
            }
        }
    }

#pragma unroll
    for (int oo = 0; oo < 64; oo++)
        out[((size_t)b * 64 + oo) * HWSZ + p] = acc[oo];
}

// ---------------- launch ----------------
extern "C" void kernel_launch(void* const* d_in, const int* in_sizes, int n_in,
                              void* d_out, int out_size) {
    const float* x          = (const float*)d_in[0];
    const float* extra_feat = (const float*)d_in[1];
    const float* flow       = (const float*)d_in[2];
    const float* w1         = (const float*)d_in[3];
    const float* b1         = (const float*)d_in[4];
    const float* w2         = (const float*)d_in[5];
    const float* b2         = (const float*)d_in[6];
    const float* w3         = (const float*)d_in[7];
    const float* b3         = (const float*)d_in[8];
    const float* weight     = (const float*)d_in[9];
    float* out = (float*)d_out;

    float *h1, *h2, *obuf;
    float4* xt;
    cudaGetSymbolAddress((void**)&h1, g_h1);
    cudaGetSymbolAddress((void**)&h2, g_h2);
    cudaGetSymbolAddress((void**)&obuf, g_o);
    cudaGetSymbolAddress((void**)&xt, g_xt);

    transpose_x_kernel<<<(2 * 16 * HWSZ + 255) / 256, 256>>>(x, xt);

    // conv1: 128 -> 64, leaky
    conv3x3_kernel<true><<<dim3(16, 64 / OCB, 2), 256>>>(extra_feat, w1, b1, h1, 128, 64);
    // conv2: 64 -> 64, leaky
    conv3x3_kernel<true><<<dim3(16, 64 / OCB, 2), 256>>>(h1, w2, b2, h2, 64, 64);
    // conv3: 64 -> 432, linear
    conv3x3_kernel<false><<<dim3(16, 432 / OCB, 2), 256>>>(h2, w3, b3, obuf, 64, 432);

    // deformable gather + contraction
    deform_kernel<<<dim3(HWSZ / 128, 2), 128>>>(xt, obuf, flow, weight, out);
}

// round 11
// speedup vs baseline: 1.8476x; 1.1536x over previous
#include <cuda_runtime.h>

#define HH 128
#define WW 128
#define HWSZ (HH * WW)

// padded geometry: rows 130, row-stride 132; interior pixel (y,x) at (y+1)*132 + (x+2)
#define PW 132
#define PH 130
#define PHW (PH * PW)
#define POFF (PW + 2)

// ---------------- scratch (static device arrays; zero-initialized => halo stays 0) ----
__device__ float  g_efp[2 * 128 * PHW];         // padded extra_feat
__device__ float  g_h1p[2 * 64 * PHW];          // padded conv1 out
__device__ float  g_h2p[2 * 64 * PHW];          // padded conv2 out
__device__ float  g_o  [2 * 432 * HWSZ];        // conv3 out (flat, offsets/mask logits)
__device__ float4 g_xt [2 * 16 * HWSZ];         // x transposed to [B,G,H,W,cg=4]

// ---------------- pad copy: [BC,128,128] -> [BC,130,132] interior ----------------
__global__ void pad_kernel(const float* __restrict__ in, float* __restrict__ outp, int nbc) {
    int idx = blockIdx.x * 256 + threadIdx.x;
    if (idx >= nbc * HWSZ) return;
    int p = idx & (HWSZ - 1);
    int bc = idx >> 14;
    int y = p >> 7;
    int x = p & 127;
    outp[(size_t)bc * PHW + (y + 1) * PW + x + 2] = in[idx];
}

// ---------------- conv 3x3, pad 1, stride 1, fp32 (R1 microkernel, padded input) ----
// tile 32x32 output pixels, 256 threads (16x16), 2x2 px/thread, OCB=8, CCHUNK=8.
constexpr int TILE = 32;
constexpr int OCB = 8;
constexpr int CCHUNK = 8;

template <bool LEAKY>
__global__ __launch_bounds__(256, 2)
void conv3x3_kernel(const float* __restrict__ in,    // padded [B*Cin, PH, PW]
                    const float* __restrict__ wgt,
                    const float* __restrict__ bias,
                    float* __restrict__ out,          // stride OS, base OB
                    int Cin, int Cout, int OS, int OB, size_t out_chan_sz) {
    __shared__ float s_in[CCHUNK][34][36];
    __shared__ float s_w[OCB][CCHUNK][9];

    const int tid = threadIdx.x;
    const int tx = tid & 15;
    const int ty = tid >> 4;
    const int tile_id = blockIdx.x;                  // 16 tiles (4x4)
    const int y0 = (tile_id / (WW / TILE)) * TILE;
    const int x0 = (tile_id % (WW / TILE)) * TILE;
    const int ocb = blockIdx.y;
    const int b = blockIdx.z;

    const float* in_b = in + (size_t)b * Cin * PHW;

    float acc[OCB][4];
#pragma unroll
    for (int i = 0; i < OCB; i++) {
        acc[i][0] = 0.f; acc[i][1] = 0.f; acc[i][2] = 0.f; acc[i][3] = 0.f;
    }

    const int s_ch = tid >> 5;        // 0..7: channel this thread stages
    const int s_ln = tid & 31;        // lane within channel

    for (int c0 = 0; c0 < Cin; c0 += CCHUNK) {
        __syncthreads();
        // ---- stage input chunk: predicate-free copy from padded buffer ----
        // element (r,c) of tile halo = padded offset (y0+r)*PW + (x0+c+1)
        {
            const float* src = in_b + (size_t)(c0 + s_ch) * PHW + y0 * PW + x0 + 1;
#pragma unroll 2
            for (int r = 0; r < 34; r++) {
                const float* row = src + r * PW;
                s_in[s_ch][r][s_ln] = row[s_ln];
                if (s_ln < 2)
                    s_in[s_ch][r][32 + s_ln] = row[32 + s_ln];
            }
        }
        // ---- stage weights: OCB x CCHUNK x 9 ----
        for (int idx = tid; idx < OCB * CCHUNK * 9; idx += 256) {
            int oc = idx / (CCHUNK * 9);
            int rem = idx - oc * (CCHUNK * 9);
            int ci = rem / 9;
            int k = rem - ci * 9;
            s_w[oc][ci][k] = wgt[(size_t)((ocb * OCB + oc) * Cin + c0 + ci) * 9 + k];
        }
        __syncthreads();

#pragma unroll
        for (int ci = 0; ci < CCHUNK; ci++) {
            float iv[4][4];
#pragma unroll
            for (int dy = 0; dy < 4; dy++)
#pragma unroll
                for (int dx = 0; dx < 4; dx++)
                    iv[dy][dx] = s_in[ci][2 * ty + dy][2 * tx + dx];
#pragma unroll
            for (int oc = 0; oc < OCB; oc++) {
#pragma unroll
                for (int ky = 0; ky < 3; ky++)
#pragma unroll
                    for (int kx = 0; kx < 3; kx++) {
                        float w = s_w[oc][ci][ky * 3 + kx];
                        acc[oc][0] = fmaf(iv[ky][kx],         w, acc[oc][0]);
                        acc[oc][1] = fmaf(iv[ky][kx + 1],     w, acc[oc][1]);
                        acc[oc][2] = fmaf(iv[ky + 1][kx],     w, acc[oc][2]);
                        acc[oc][3] = fmaf(iv[ky + 1][kx + 1], w, acc[oc][3]);
                    }
            }
        }
    }

    const int oy = y0 + 2 * ty;
    const int ox = x0 + 2 * tx;
#pragma unroll
    for (int oc = 0; oc < OCB; oc++) {
        float bv = bias[ocb * OCB + oc];
        float* op = out + (size_t)(b * Cout + ocb * OCB + oc) * out_chan_sz + OB;
#pragma unroll
        for (int q = 0; q < 4; q++) {
            float v = acc[oc][q] + bv;
            if (LEAKY) v = (v >= 0.f) ? v : 0.1f * v;
            int yy = oy + (q >> 1);
            int xx = ox + (q & 1);
            op[yy * OS + xx] = v;
        }
    }
}

// ---------------- x transpose: [B,64,H,W] -> [B,16,H,W,4] ----------------
__global__ void transpose_x_kernel(const float* __restrict__ x, float4* __restrict__ xt) {
    int idx = blockIdx.x * 256 + threadIdx.x;
    if (idx >= 2 * 16 * HWSZ) return;
    int p = idx & (HWSZ - 1);
    int bg = idx / HWSZ;
    const float* src = x + (size_t)bg * 4 * HWSZ + p;
    float4 v;
    v.x = src[0];
    v.y = src[HWSZ];
    v.z = src[2 * HWSZ];
    v.w = src[3 * HWSZ];
    xt[idx] = v;
}

// ---------------- deformable gather + per-pixel [64 x 576] contraction [R1-exact] ----
__global__ __launch_bounds__(128, 3)
void deform_kernel(const float4* __restrict__ xt,     // [B,16,HW] float4
                   const float* __restrict__ o,       // [B,432,HW]
                   const float* __restrict__ flow,    // [B,2,HW]
                   const float* __restrict__ weight,  // [64,64,9]
                   float* __restrict__ out) {         // [B,64,HW]
    __shared__ __align__(16) float s_w[64 * 36];

    const int tid = threadIdx.x;
    const int b = blockIdx.y;
    const int p = blockIdx.x * 128 + tid;
    const int h = p >> 7;
    const int w = p & 127;

    const float* ob = o + (size_t)b * 432 * HWSZ + p;
    const float fy = flow[((size_t)b * 2 + 1) * HWSZ + p];
    const float fx = flow[((size_t)b * 2 + 0) * HWSZ + p];

    float acc[64];
#pragma unroll
    for (int i = 0; i < 64; i++) acc[i] = 0.f;

    for (int g = 0; g < 16; g++) {
        __syncthreads();
        for (int idx = tid; idx < 64 * 36; idx += 128) {
            int oo = idx / 36;
            int m = idx - oo * 36;
            s_w[idx] = weight[(size_t)oo * 576 + g * 36 + m];
        }
        __syncthreads();

        const float4* xg = xt + (size_t)(b * 16 + g) * HWSZ;
        float val[36];

#pragma unroll
        for (int k = 0; k < 9; k++) {
            float lo_y = ob[(size_t)(g * 18 + 2 * k) * HWSZ];
            float lo_x = ob[(size_t)(g * 18 + 2 * k + 1) * HWSZ];
            float lo_m = ob[(size_t)(288 + g * 9 + k) * HWSZ];

            float offy = 10.f * tanhf(lo_y) + fy;
            float offx = 10.f * tanhf(lo_x) + fx;
            float msk = 1.f / (1.f + expf(-lo_m));

            float py = (float)(h + (k / 3) - 1) + offy;
            float px = (float)(w + (k % 3) - 1) + offx;

            float y0f = floorf(py);
            float x0f = floorf(px);
            float wy = py - y0f;
            float wx = px - x0f;
            int y0 = (int)y0f;
            int x0 = (int)x0f;

            bool y0v = ((unsigned)y0 < HH);
            bool y1v = ((unsigned)(y0 + 1) < HH);
            bool x0v = ((unsigned)x0 < WW);
            bool x1v = ((unsigned)(x0 + 1) < WW);

            float4 v00 = make_float4(0.f, 0.f, 0.f, 0.f);
            float4 v01 = v00, v10 = v00, v11 = v00;
            if (y0v && x0v) v00 = __ldg(&xg[y0 * WW + x0]);
            if (y0v && x1v) v01 = __ldg(&xg[y0 * WW + x0 + 1]);
            if (y1v && x0v) v10 = __ldg(&xg[(y0 + 1) * WW + x0]);
            if (y1v && x1v) v11 = __ldg(&xg[(y0 + 1) * WW + x0 + 1]);

            float w00 = (1.f - wy) * (1.f - wx);
            float w01 = (1.f - wy) * wx;
            float w10 = wy * (1.f - wx);
            float w11 = wy * wx;

            val[0 * 9 + k] = msk * (w00 * v00.x + w01 * v01.x + w10 * v10.x + w11 * v11.x);
            val[1 * 9 + k] = msk * (w00 * v00.y + w01 * v01.y + w10 * v10.y + w11 * v11.y);
            val[2 * 9 + k] = msk * (w00 * v00.z + w01 * v01.z + w10 * v10.z + w11 * v11.z);
            val[3 * 9 + k] = msk * (w00 * v00.w + w01 * v01.w + w10 * v10.w + w11 * v11.w);
        }

        const float4* sw4 = (const float4*)s_w;
#pragma unroll
        for (int oo = 0; oo < 64; oo++) {
#pragma unroll
            for (int m4 = 0; m4 < 9; m4++) {
                float4 w4 = sw4[oo * 9 + m4];
                acc[oo] = fmaf(val[m4 * 4 + 0], w4.x, acc[oo]);
                acc[oo] = fmaf(val[m4 * 4 + 1], w4.y, acc[oo]);
                acc[oo] = fmaf(val[m4 * 4 + 2], w4.z, acc[oo]);
                acc[oo] = fmaf(val[m4 * 4 + 3], w4.w, acc[oo]);
            }
        }
    }

#pragma unroll
    for (int oo = 0; oo < 64; oo++)
        out[((size_t)b * 64 + oo) * HWSZ + p] = acc[oo];
}

// ---------------- launch ----------------
extern "C" void kernel_launch(void* const* d_in, const int* in_sizes, int n_in,
                              void* d_out, int out_size) {
    const float* x          = (const float*)d_in[0];
    const float* extra_feat = (const float*)d_in[1];
    const float* flow       = (const float*)d_in[2];
    const float* w1         = (const float*)d_in[3];
    const float* b1         = (const float*)d_in[4];
    const float* w2         = (const float*)d_in[5];
    const float* b2         = (const float*)d_in[6];
    const float* w3         = (const float*)d_in[7];
    const float* b3         = (const float*)d_in[8];
    const float* weight     = (const float*)d_in[9];
    float* out = (float*)d_out;

    float *efp, *h1p, *h2p, *obuf;
    float4* xt;
    cudaGetSymbolAddress((void**)&efp, g_efp);
    cudaGetSymbolAddress((void**)&h1p, g_h1p);
    cudaGetSymbolAddress((void**)&h2p, g_h2p);
    cudaGetSymbolAddress((void**)&obuf, g_o);
    cudaGetSymbolAddress((void**)&xt, g_xt);

    // pad extra_feat into halo layout (ring stays zero from static init)
    pad_kernel<<<(2 * 128 * HWSZ + 255) / 256, 256>>>(extra_feat, efp, 2 * 128);

    // x -> channels-last-per-group copy (for float4 gathers)
    transpose_x_kernel<<<(2 * 16 * HWSZ + 255) / 256, 256>>>(x, xt);

    // conv1: 128 -> 64, leaky, padded in -> padded out
    conv3x3_kernel<true><<<dim3(16, 64 / OCB, 2), 256>>>(
        efp, w1, b1, h1p, 128, 64, PW, POFF, (size_t)PHW);
    // conv2: 64 -> 64, leaky, padded -> padded
    conv3x3_kernel<true><<<dim3(16, 64 / OCB, 2), 256>>>(
        h1p, w2, b2, h2p, 64, 64, PW, POFF, (size_t)PHW);
    // conv3: 64 -> 432, linear, padded -> flat
    conv3x3_kernel<false><<<dim3(16, 432 / OCB, 2), 256>>>(
        h2p, w3, b3, obuf, 64, 432, WW, 0, (size_t)HWSZ);

    // deformable gather + contraction
    deform_kernel<<<dim3(HWSZ / 128, 2), 128>>>(xt, obuf, flow, weight, out);
}

// round 12
// speedup vs baseline: 2.4944x; 1.3501x over previous
#include <cuda_runtime.h>
#include <cstdint>

#define HH 128
#define WW 128
#define HWSZ (HH * WW)

// padded geometry: 130 rows x 136 cols; interior pixel (y,x) at (y+1)*136 + (x+4).
// 4-col left halo => tile stage base (x0-4 -> padded col x0) is 16B aligned.
#define PW 136
#define PH 130
#define PHW (PH * PW)

// ---------------- scratch (zero-initialized device globals; halo ring never written) ----
__device__ float  g_efp[2 * 128 * PHW];
__device__ float  g_h1p[2 * 64 * PHW];
__device__ float  g_h2p[2 * 64 * PHW];
__device__ float  g_o  [2 * 432 * HWSZ];
__device__ float4 g_xt [2 * 16 * HWSZ];

// ---------------- cp.async helpers ----------------
__device__ __forceinline__ unsigned su32(const void* p) {
    return (unsigned)__cvta_generic_to_shared(p);
}
__device__ __forceinline__ void cpa16(unsigned d, const void* s) {
    asm volatile("cp.async.ca.shared.global [%0], [%1], 16;" :: "r"(d), "l"(s));
}
__device__ __forceinline__ void cpa4(unsigned d, const void* s) {
    asm volatile("cp.async.ca.shared.global [%0], [%1], 4;" :: "r"(d), "l"(s));
}
__device__ __forceinline__ void cpcommit() { asm volatile("cp.async.commit_group;"); }
__device__ __forceinline__ void cpwait0()  { asm volatile("cp.async.wait_group 0;"); }
__device__ __forceinline__ void cpwait1()  { asm volatile("cp.async.wait_group 1;"); }

// ---------------- pad copy: [BC,128,128] -> padded [BC,130,136] interior ----------------
__global__ void pad_kernel(const float* __restrict__ in, float* __restrict__ outp, int n) {
    int idx = blockIdx.x * 256 + threadIdx.x;
    if (idx >= n) return;
    int p = idx & (HWSZ - 1);
    int bc = idx >> 14;
    int y = p >> 7;
    int x = p & 127;
    outp[(size_t)bc * PHW + (y + 1) * PW + x + 4] = in[idx];
}

// ---------------- conv 3x3 fp32, cp.async double-buffered staging ----------------
// tile 32x32, 256 threads, 2x2 px/thread, OCB=8, CCHUNK=8 (R1 compute core).
constexpr int SIN_BUF = 8 * 34 * 40;           // floats per input buffer
constexpr int SW_BUF  = 8 * 8 * 9;             // floats per weight buffer
constexpr int SMEM_CONV = (2 * SIN_BUF + 2 * SW_BUF) * 4;

template <bool LEAKY>
__global__ __launch_bounds__(256, 2)
void conv3x3_kernel(const float* __restrict__ in,    // padded [B*Cin, PH, PW]
                    const float* __restrict__ wgt,
                    const float* __restrict__ bias,
                    float* __restrict__ out,
                    int Cin, int Cout, int OS, int OB, size_t ocs) {
    extern __shared__ float smem[];
    float* s_in = smem;                 // [2][8][34][40]
    float* s_w  = smem + 2 * SIN_BUF;   // [2][8 oc][8 ci][9]

    const int tid = threadIdx.x;
    const int tx = tid & 15;
    const int ty = tid >> 4;
    const int tile = blockIdx.x;                 // 4x4 tiles
    const int y0 = (tile >> 2) * 32;
    const int x0 = (tile & 3) * 32;
    const int ocb = blockIdx.y;
    const int b = blockIdx.z;

    const float* in_b = in + (size_t)b * Cin * PHW;
    const int s_ch = tid >> 5;       // 0..7
    const int s_ln = tid & 31;

    float acc[8][4];
#pragma unroll
    for (int i = 0; i < 8; i++) {
        acc[i][0] = 0.f; acc[i][1] = 0.f; acc[i][2] = 0.f; acc[i][3] = 0.f;
    }

    auto stage = [&](int c0, int bufi) {
        // input: rows y0..y0+33 (padded), cols x0..x0+39 (padded) — all 16B aligned
        const float* src = in_b + (size_t)(c0 + s_ch) * PHW + y0 * PW + x0;
        float* dst = s_in + (size_t)(bufi * 8 + s_ch) * (34 * 40);
        for (int idx = s_ln; idx < 340; idx += 32) {
            int r = idx / 10;
            int q = idx - r * 10;
            cpa16(su32(dst + r * 40 + q * 4), src + r * PW + q * 4);
        }
        // weights: 8 oc x 8 ci x 9
        for (int idx = tid; idx < 576; idx += 256) {
            int oc = idx / 72;
            int rem = idx - oc * 72;
            int ci = rem / 9;
            int k = rem - ci * 9;
            cpa4(su32(s_w + bufi * SW_BUF + (oc * 8 + ci) * 9 + k),
                 wgt + ((size_t)(ocb * 8 + oc) * Cin + c0 + ci) * 9 + k);
        }
    };

    stage(0, 0);
    cpcommit();

    int buf = 0;
    for (int c0 = 0; c0 < Cin; c0 += 8) {
        if (c0 + 8 < Cin) {
            stage(c0 + 8, buf ^ 1);
            cpcommit();
            cpwait1();
        } else {
            cpwait0();
        }
        __syncthreads();

        const float* si = s_in + buf * SIN_BUF;
        const float* sw = s_w + buf * SW_BUF;
#pragma unroll
        for (int ci = 0; ci < 8; ci++) {
            const float* sc = si + ci * (34 * 40);
            float iv[4][4];
#pragma unroll
            for (int dy = 0; dy < 4; dy++)
#pragma unroll
                for (int dx = 0; dx < 4; dx++)
                    iv[dy][dx] = sc[(2 * ty + dy) * 40 + 2 * tx + dx + 3];
#pragma unroll
            for (int oc = 0; oc < 8; oc++) {
#pragma unroll
                for (int ky = 0; ky < 3; ky++)
#pragma unroll
                    for (int kx = 0; kx < 3; kx++) {
                        float w = sw[(oc * 8 + ci) * 9 + ky * 3 + kx];
                        acc[oc][0] = fmaf(iv[ky][kx],         w, acc[oc][0]);
                        acc[oc][1] = fmaf(iv[ky][kx + 1],     w, acc[oc][1]);
                        acc[oc][2] = fmaf(iv[ky + 1][kx],     w, acc[oc][2]);
                        acc[oc][3] = fmaf(iv[ky + 1][kx + 1], w, acc[oc][3]);
                    }
            }
        }
        __syncthreads();   // guard buf^1 overwrite by next stage
        buf ^= 1;
    }

    const int oy = y0 + 2 * ty;
    const int ox = x0 + 2 * tx;
#pragma unroll
    for (int oc = 0; oc < 8; oc++) {
        float bv = bias[ocb * 8 + oc];
        float* op = out + (size_t)(b * Cout + ocb * 8 + oc) * ocs + OB;
#pragma unroll
        for (int q = 0; q < 4; q++) {
            float v = acc[oc][q] + bv;
            if (LEAKY) v = (v >= 0.f) ? v : 0.1f * v;
            int yy = oy + (q >> 1);
            int xx = ox + (q & 1);
            op[yy * OS + xx] = v;
        }
    }
}

// ---------------- x transpose: [B,64,H,W] -> [B,16,H,W,4] ----------------
__global__ void transpose_x_kernel(const float* __restrict__ x, float4* __restrict__ xt) {
    int idx = blockIdx.x * 256 + threadIdx.x;
    if (idx >= 2 * 16 * HWSZ) return;
    int p = idx & (HWSZ - 1);
    int bg = idx / HWSZ;
    const float* src = x + (size_t)bg * 4 * HWSZ + p;
    float4 v;
    v.x = src[0];
    v.y = src[HWSZ];
    v.z = src[2 * HWSZ];
    v.w = src[3 * HWSZ];
    xt[idx] = v;
}

// ---------------- deformable gather + block GEMM contraction ----------------
// Per block: 128 pixels. Per group g: gather val -> s_val[36][128]; weights (cp.async)
// -> s_w[36][64]; then register-tiled GEMM, each thread owns 8oc x 8px.
__global__ __launch_bounds__(128, 3)
void deform_kernel(const float4* __restrict__ xt,
                   const float* __restrict__ o,
                   const float* __restrict__ flow,
                   const float* __restrict__ weight,   // [64][576]
                   float* __restrict__ out) {
    __shared__ __align__(16) float s_w[36 * 64];
    __shared__ __align__(16) float s_val[36 * 128];

    const int tid = threadIdx.x;
    const int b = blockIdx.y;
    const int p0 = blockIdx.x * 128;
    const int p = p0 + tid;                 // gather pixel for this thread
    const int h = p >> 7;
    const int w = p & 127;
    const int px0 = (tid & 15) * 8;         // GEMM pixel tile base (within block)
    const int oc0 = (tid >> 4) * 8;         // GEMM oc tile base

    const float* ob = o + (size_t)b * 432 * HWSZ + p;
    const float fy = flow[((size_t)b * 2 + 1) * HWSZ + p];
    const float fx = flow[((size_t)b * 2 + 0) * HWSZ + p];

    float acc[8][8];
#pragma unroll
    for (int i = 0; i < 8; i++)
#pragma unroll
        for (int j = 0; j < 8; j++) acc[i][j] = 0.f;

    for (int g = 0; g < 16; g++) {
        // prefetch weights for this group (async; consumed after gather phase)
        for (int idx = tid; idx < 36 * 64; idx += 128) {
            int m = idx >> 6;
            int oo = idx & 63;
            cpa4(su32(s_w + idx), weight + (size_t)oo * 576 + g * 36 + m);
        }
        cpcommit();

        // gather phase: this thread's pixel, 9 taps x 4 channels -> s_val[m][tid]
        const float4* xg = xt + (size_t)(b * 16 + g) * HWSZ;
#pragma unroll
        for (int k = 0; k < 9; k++) {
            float lo_y = ob[(size_t)(g * 18 + 2 * k) * HWSZ];
            float lo_x = ob[(size_t)(g * 18 + 2 * k + 1) * HWSZ];
            float lo_m = ob[(size_t)(288 + g * 9 + k) * HWSZ];

            float offy = 10.f * tanhf(lo_y) + fy;
            float offx = 10.f * tanhf(lo_x) + fx;
            float msk = 1.f / (1.f + expf(-lo_m));

            float py = (float)(h + (k / 3) - 1) + offy;
            float px = (float)(w + (k % 3) - 1) + offx;

            float y0f = floorf(py);
            float x0f = floorf(px);
            float wy = py - y0f;
            float wx = px - x0f;
            int y0 = (int)y0f;
            int x0 = (int)x0f;

            bool y0v = ((unsigned)y0 < HH);
            bool y1v = ((unsigned)(y0 + 1) < HH);
            bool x0v = ((unsigned)x0 < WW);
            bool x1v = ((unsigned)(x0 + 1) < WW);

            float4 v00 = make_float4(0.f, 0.f, 0.f, 0.f);
            float4 v01 = v00, v10 = v00, v11 = v00;
            if (y0v && x0v) v00 = __ldg(&xg[y0 * WW + x0]);
            if (y0v && x1v) v01 = __ldg(&xg[y0 * WW + x0 + 1]);
            if (y1v && x0v) v10 = __ldg(&xg[(y0 + 1) * WW + x0]);
            if (y1v && x1v) v11 = __ldg(&xg[(y0 + 1) * WW + x0 + 1]);

            float w00 = (1.f - wy) * (1.f - wx);
            float w01 = (1.f - wy) * wx;
            float w10 = wy * (1.f - wx);
            float w11 = wy * wx;

            s_val[(0 * 9 + k) * 128 + tid] = msk * (w00 * v00.x + w01 * v01.x + w10 * v10.x + w11 * v11.x);
            s_val[(1 * 9 + k) * 128 + tid] = msk * (w00 * v00.y + w01 * v01.y + w10 * v10.y + w11 * v11.y);
            s_val[(2 * 9 + k) * 128 + tid] = msk * (w00 * v00.z + w01 * v01.z + w10 * v10.z + w11 * v11.z);
            s_val[(3 * 9 + k) * 128 + tid] = msk * (w00 * v00.w + w01 * v01.w + w10 * v10.w + w11 * v11.w);
        }

        cpwait0();
        __syncthreads();

        // GEMM: acc[8 oc][8 px] += W[m][oc] * V[m][px]
#pragma unroll
        for (int m = 0; m < 36; m++) {
            float4 wa = *(const float4*)(s_w + m * 64 + oc0);
            float4 wb = *(const float4*)(s_w + m * 64 + oc0 + 4);
            float4 va = *(const float4*)(s_val + m * 128 + px0);
            float4 vb = *(const float4*)(s_val + m * 128 + px0 + 4);
            float wv[8] = { wa.x, wa.y, wa.z, wa.w, wb.x, wb.y, wb.z, wb.w };
            float vv[8] = { va.x, va.y, va.z, va.w, vb.x, vb.y, vb.z, vb.w };
#pragma unroll
            for (int i = 0; i < 8; i++)
#pragma unroll
                for (int j = 0; j < 8; j++)
                    acc[i][j] = fmaf(wv[i], vv[j], acc[i][j]);
        }
        __syncthreads();   // guard s_w/s_val overwrite next group
    }

#pragma unroll
    for (int i = 0; i < 8; i++) {
        float* op = out + ((size_t)b * 64 + oc0 + i) * HWSZ + p0 + px0;
        float4 o0 = make_float4(acc[i][0], acc[i][1], acc[i][2], acc[i][3]);
        float4 o1 = make_float4(acc[i][4], acc[i][5], acc[i][6], acc[i][7]);
        *(float4*)op = o0;
        *(float4*)(op + 4) = o1;
    }
}

// ---------------- launch ----------------
extern "C" void kernel_launch(void* const* d_in, const int* in_sizes, int n_in,
                              void* d_out, int out_size) {
    const float* x          = (const float*)d_in[0];
    const float* extra_feat = (const float*)d_in[1];
    const float* flow       = (const float*)d_in[2];
    const float* w1         = (const float*)d_in[3];
    const float* b1         = (const float*)d_in[4];
    const float* w2         = (const float*)d_in[5];
    const float* b2         = (const float*)d_in[6];
    const float* w3         = (const float*)d_in[7];
    const float* b3         = (const float*)d_in[8];
    const float* weight     = (const float*)d_in[9];
    float* out = (float*)d_out;

    float *efp, *h1p, *h2p, *obuf;
    float4* xt;
    cudaGetSymbolAddress((void**)&efp, g_efp);
    cudaGetSymbolAddress((void**)&h1p, g_h1p);
    cudaGetSymbolAddress((void**)&h2p, g_h2p);
    cudaGetSymbolAddress((void**)&obuf, g_o);
    cudaGetSymbolAddress((void**)&xt, g_xt);

    cudaFuncSetAttribute(conv3x3_kernel<true>,
                         cudaFuncAttributeMaxDynamicSharedMemorySize, SMEM_CONV);
    cudaFuncSetAttribute(conv3x3_kernel<false>,
                         cudaFuncAttributeMaxDynamicSharedMemorySize, SMEM_CONV);

    pad_kernel<<<(2 * 128 * HWSZ + 255) / 256, 256>>>(extra_feat, efp, 2 * 128 * HWSZ);
    transpose_x_kernel<<<(2 * 16 * HWSZ + 255) / 256, 256>>>(x, xt);

    // conv1: 128 -> 64, leaky, padded -> padded
    conv3x3_kernel<true><<<dim3(16, 8, 2), 256, SMEM_CONV>>>(
        efp, w1, b1, h1p, 128, 64, PW, PW + 4, (size_t)PHW);
    // conv2: 64 -> 64, leaky, padded -> padded
    conv3x3_kernel<true><<<dim3(16, 8, 2), 256, SMEM_CONV>>>(
        h1p, w2, b2, h2p, 64, 64, PW, PW + 4, (size_t)PHW);
    // conv3: 64 -> 432, linear, padded -> flat
    conv3x3_kernel<false><<<dim3(16, 54, 2), 256, SMEM_CONV>>>(
        h2p, w3, b3, obuf, 64, 432, WW, 0, (size_t)HWSZ);

    // deform: gather + block GEMM
    deform_kernel<<<dim3(HWSZ / 128, 2), 128>>>(xt, obuf, flow, weight, out);
}

// round 13
// speedup vs baseline: 2.5436x; 1.0197x over previous
#include <cuda_runtime.h>
#include <cstdint>

#define HH 128
#define WW 128
#define HWSZ (HH * WW)

// padded geometry: 130 rows x 136 cols; interior pixel (y,x) at (y+1)*136 + (x+4).
#define PW 136
#define PH 130
#define PHW (PH * PW)

#define GSPLIT 4   // deform group-split factor (16 groups / 4 per block)

// ---------------- scratch (zero-initialized device globals; halo ring never written) ----
__device__ float  g_efp[2 * 128 * PHW];
__device__ float  g_h1p[2 * 64 * PHW];
__device__ float  g_h2p[2 * 64 * PHW];
__device__ float  g_o  [2 * 432 * HWSZ];
__device__ float4 g_xt [2 * 16 * HWSZ];
__device__ float  g_part[2 * GSPLIT * 64 * HWSZ];   // deform partial sums

// ---------------- cp.async helpers ----------------
__device__ __forceinline__ unsigned su32(const void* p) {
    return (unsigned)__cvta_generic_to_shared(p);
}
__device__ __forceinline__ void cpa16(unsigned d, const void* s) {
    asm volatile("cp.async.ca.shared.global [%0], [%1], 16;" :: "r"(d), "l"(s));
}
__device__ __forceinline__ void cpa4(unsigned d, const void* s) {
    asm volatile("cp.async.ca.shared.global [%0], [%1], 4;" :: "r"(d), "l"(s));
}
__device__ __forceinline__ void cpcommit() { asm volatile("cp.async.commit_group;"); }
__device__ __forceinline__ void cpwait0()  { asm volatile("cp.async.wait_group 0;"); }
__device__ __forceinline__ void cpwait1()  { asm volatile("cp.async.wait_group 1;"); }

// ---------------- pad copy: [BC,128,128] -> padded [BC,130,136] interior ----------------
__global__ void pad_kernel(const float* __restrict__ in, float* __restrict__ outp, int n) {
    int idx = blockIdx.x * 256 + threadIdx.x;
    if (idx >= n) return;
    int p = idx & (HWSZ - 1);
    int bc = idx >> 14;
    int y = p >> 7;
    int x = p & 127;
    outp[(size_t)bc * PHW + (y + 1) * PW + x + 4] = in[idx];
}

// ---------------- conv 3x3 fp32, cp.async double-buffered staging (R10 winner) ----------
constexpr int SIN_BUF = 8 * 34 * 40;
constexpr int SW_BUF  = 8 * 8 * 9;
constexpr int SMEM_CONV = (2 * SIN_BUF + 2 * SW_BUF) * 4;

template <bool LEAKY>
__global__ __launch_bounds__(256, 2)
void conv3x3_kernel(const float* __restrict__ in,
                    const float* __restrict__ wgt,
                    const float* __restrict__ bias,
                    float* __restrict__ out,
                    int Cin, int Cout, int OS, int OB, size_t ocs) {
    extern __shared__ float smem[];
    float* s_in = smem;
    float* s_w  = smem + 2 * SIN_BUF;

    const int tid = threadIdx.x;
    const int tx = tid & 15;
    const int ty = tid >> 4;
    const int tile = blockIdx.x;
    const int y0 = (tile >> 2) * 32;
    const int x0 = (tile & 3) * 32;
    const int ocb = blockIdx.y;
    const int b = blockIdx.z;

    const float* in_b = in + (size_t)b * Cin * PHW;
    const int s_ch = tid >> 5;
    const int s_ln = tid & 31;

    float acc[8][4];
#pragma unroll
    for (int i = 0; i < 8; i++) {
        acc[i][0] = 0.f; acc[i][1] = 0.f; acc[i][2] = 0.f; acc[i][3] = 0.f;
    }

    auto stage = [&](int c0, int bufi) {
        const float* src = in_b + (size_t)(c0 + s_ch) * PHW + y0 * PW + x0;
        float* dst = s_in + (size_t)(bufi * 8 + s_ch) * (34 * 40);
        for (int idx = s_ln; idx < 340; idx += 32) {
            int r = idx / 10;
            int q = idx - r * 10;
            cpa16(su32(dst + r * 40 + q * 4), src + r * PW + q * 4);
        }
        for (int idx = tid; idx < 576; idx += 256) {
            int oc = idx / 72;
            int rem = idx - oc * 72;
            int ci = rem / 9;
            int k = rem - ci * 9;
            cpa4(su32(s_w + bufi * SW_BUF + (oc * 8 + ci) * 9 + k),
                 wgt + ((size_t)(ocb * 8 + oc) * Cin + c0 + ci) * 9 + k);
        }
    };

    stage(0, 0);
    cpcommit();

    int buf = 0;
    for (int c0 = 0; c0 < Cin; c0 += 8) {
        if (c0 + 8 < Cin) {
            stage(c0 + 8, buf ^ 1);
            cpcommit();
            cpwait1();
        } else {
            cpwait0();
        }
        __syncthreads();

        const float* si = s_in + buf * SIN_BUF;
        const float* sw = s_w + buf * SW_BUF;
#pragma unroll
        for (int ci = 0; ci < 8; ci++) {
            const float* sc = si + ci * (34 * 40);
            float iv[4][4];
#pragma unroll
            for (int dy = 0; dy < 4; dy++)
#pragma unroll
                for (int dx = 0; dx < 4; dx++)
                    iv[dy][dx] = sc[(2 * ty + dy) * 40 + 2 * tx + dx + 3];
#pragma unroll
            for (int oc = 0; oc < 8; oc++) {
#pragma unroll
                for (int ky = 0; ky < 3; ky++)
#pragma unroll
                    for (int kx = 0; kx < 3; kx++) {
                        float w = sw[(oc * 8 + ci) * 9 + ky * 3 + kx];
                        acc[oc][0] = fmaf(iv[ky][kx],         w, acc[oc][0]);
                        acc[oc][1] = fmaf(iv[ky][kx + 1],     w, acc[oc][1]);
                        acc[oc][2] = fmaf(iv[ky + 1][kx],     w, acc[oc][2]);
                        acc[oc][3] = fmaf(iv[ky + 1][kx + 1], w, acc[oc][3]);
                    }
            }
        }
        __syncthreads();
        buf ^= 1;
    }

    const int oy = y0 + 2 * ty;
    const int ox = x0 + 2 * tx;
#pragma unroll
    for (int oc = 0; oc < 8; oc++) {
        float bv = bias[ocb * 8 + oc];
        float* op = out + (size_t)(b * Cout + ocb * 8 + oc) * ocs + OB;
#pragma unroll
        for (int q = 0; q < 4; q++) {
            float v = acc[oc][q] + bv;
            if (LEAKY) v = (v >= 0.f) ? v : 0.1f * v;
            int yy = oy + (q >> 1);
            int xx = ox + (q & 1);
            op[yy * OS + xx] = v;
        }
    }
}

// ---------------- x transpose: [B,64,H,W] -> [B,16,H,W,4] ----------------
__global__ void transpose_x_kernel(const float* __restrict__ x, float4* __restrict__ xt) {
    int idx = blockIdx.x * 256 + threadIdx.x;
    if (idx >= 2 * 16 * HWSZ) return;
    int p = idx & (HWSZ - 1);
    int bg = idx / HWSZ;
    const float* src = x + (size_t)bg * 4 * HWSZ + p;
    float4 v;
    v.x = src[0];
    v.y = src[HWSZ];
    v.z = src[2 * HWSZ];
    v.w = src[3 * HWSZ];
    xt[idx] = v;
}

// ---------------- deformable gather + block GEMM, group-split partials ----------------
// gridDim = (128 px-blocks, GSPLIT, 2 batches). Each block: 4 groups, 128 pixels,
// writes partial [64 oc][128 px] slice to g_part[b][split][oc][px].
__global__ __launch_bounds__(128, 3)
void deform_kernel(const float4* __restrict__ xt,
                   const float* __restrict__ o,
                   const float* __restrict__ flow,
                   const float* __restrict__ weight,   // [64][576]
                   float* __restrict__ part) {
    __shared__ __align__(16) float s_w[36 * 64];
    __shared__ __align__(16) float s_val[36 * 128];

    const int tid = threadIdx.x;
    const int b = blockIdx.z;
    const int gbase = blockIdx.y * (16 / GSPLIT);
    const int p0 = blockIdx.x * 128;
    const int p = p0 + tid;
    const int h = p >> 7;
    const int w = p & 127;
    const int px0 = (tid & 15) * 8;
    const int oc0 = (tid >> 4) * 8;

    const float* ob = o + (size_t)b * 432 * HWSZ + p;
    const float fy = flow[((size_t)b * 2 + 1) * HWSZ + p];
    const float fx = flow[((size_t)b * 2 + 0) * HWSZ + p];

    float acc[8][8];
#pragma unroll
    for (int i = 0; i < 8; i++)
#pragma unroll
        for (int j = 0; j < 8; j++) acc[i][j] = 0.f;

    for (int gi = 0; gi < 16 / GSPLIT; gi++) {
        const int g = gbase + gi;
        for (int idx = tid; idx < 36 * 64; idx += 128) {
            int m = idx >> 6;
            int oo = idx & 63;
            cpa4(su32(s_w + idx), weight + (size_t)oo * 576 + g * 36 + m);
        }
        cpcommit();

        const float4* xg = xt + (size_t)(b * 16 + g) * HWSZ;
#pragma unroll
        for (int k = 0; k < 9; k++) {
            float lo_y = ob[(size_t)(g * 18 + 2 * k) * HWSZ];
            float lo_x = ob[(size_t)(g * 18 + 2 * k + 1) * HWSZ];
            float lo_m = ob[(size_t)(288 + g * 9 + k) * HWSZ];

            float offy = 10.f * tanhf(lo_y) + fy;
            float offx = 10.f * tanhf(lo_x) + fx;
            float msk = 1.f / (1.f + expf(-lo_m));

            float py = (float)(h + (k / 3) - 1) + offy;
            float px = (float)(w + (k % 3) - 1) + offx;

            float y0f = floorf(py);
            float x0f = floorf(px);
            float wy = py - y0f;
            float wx = px - x0f;
            int y0 = (int)y0f;
            int x0 = (int)x0f;

            bool y0v = ((unsigned)y0 < HH);
            bool y1v = ((unsigned)(y0 + 1) < HH);
            bool x0v = ((unsigned)x0 < WW);
            bool x1v = ((unsigned)(x0 + 1) < WW);

            float4 v00 = make_float4(0.f, 0.f, 0.f, 0.f);
            float4 v01 = v00, v10 = v00, v11 = v00;
            if (y0v && x0v) v00 = __ldg(&xg[y0 * WW + x0]);
            if (y0v && x1v) v01 = __ldg(&xg[y0 * WW + x0 + 1]);
            if (y1v && x0v) v10 = __ldg(&xg[(y0 + 1) * WW + x0]);
            if (y1v && x1v) v11 = __ldg(&xg[(y0 + 1) * WW + x0 + 1]);

            float w00 = (1.f - wy) * (1.f - wx);
            float w01 = (1.f - wy) * wx;
            float w10 = wy * (1.f - wx);
            float w11 = wy * wx;

            s_val[(0 * 9 + k) * 128 + tid] = msk * (w00 * v00.x + w01 * v01.x + w10 * v10.x + w11 * v11.x);
            s_val[(1 * 9 + k) * 128 + tid] = msk * (w00 * v00.y + w01 * v01.y + w10 * v10.y + w11 * v11.y);
            s_val[(2 * 9 + k) * 128 + tid] = msk * (w00 * v00.z + w01 * v01.z + w10 * v10.z + w11 * v11.z);
            s_val[(3 * 9 + k) * 128 + tid] = msk * (w00 * v00.w + w01 * v01.w + w10 * v10.w + w11 * v11.w);
        }

        cpwait0();
        __syncthreads();

#pragma unroll
        for (int m = 0; m < 36; m++) {
            float4 wa = *(const float4*)(s_w + m * 64 + oc0);
            float4 wb = *(const float4*)(s_w + m * 64 + oc0 + 4);
            float4 va = *(const float4*)(s_val + m * 128 + px0);
            float4 vb = *(const float4*)(s_val + m * 128 + px0 + 4);
            float wv[8] = { wa.x, wa.y, wa.z, wa.w, wb.x, wb.y, wb.z, wb.w };
            float vv[8] = { va.x, va.y, va.z, va.w, vb.x, vb.y, vb.z, vb.w };
#pragma unroll
            for (int i = 0; i < 8; i++)
#pragma unroll
                for (int j = 0; j < 8; j++)
                    acc[i][j] = fmaf(wv[i], vv[j], acc[i][j]);
        }
        __syncthreads();
    }

    float* pb = part + ((size_t)(b * GSPLIT + blockIdx.y) * 64) * HWSZ;
#pragma unroll
    for (int i = 0; i < 8; i++) {
        float* op = pb + (size_t)(oc0 + i) * HWSZ + p0 + px0;
        *(float4*)op       = make_float4(acc[i][0], acc[i][1], acc[i][2], acc[i][3]);
        *(float4*)(op + 4) = make_float4(acc[i][4], acc[i][5], acc[i][6], acc[i][7]);
    }
}

// ---------------- partial reduction: out = sum over GSPLIT partials ----------------
__global__ void reduce_kernel(const float4* __restrict__ part, float4* __restrict__ out) {
    int idx = blockIdx.x * 256 + threadIdx.x;          // over 2*64*HWSZ/4 float4s
    if (idx >= 2 * 64 * HWSZ / 4) return;
    int b = idx / (64 * HWSZ / 4);
    int r = idx - b * (64 * HWSZ / 4);                 // (oc,p4) within batch
    const float4* pp = part + (size_t)b * GSPLIT * (64 * HWSZ / 4) + r;
    float4 s = pp[0];
#pragma unroll
    for (int k = 1; k < GSPLIT; k++) {
        float4 v = pp[(size_t)k * (64 * HWSZ / 4)];
        s.x += v.x; s.y += v.y; s.z += v.z; s.w += v.w;
    }
    out[idx] = s;
}

// ---------------- launch ----------------
extern "C" void kernel_launch(void* const* d_in, const int* in_sizes, int n_in,
                              void* d_out, int out_size) {
    const float* x          = (const float*)d_in[0];
    const float* extra_feat = (const float*)d_in[1];
    const float* flow       = (const float*)d_in[2];
    const float* w1         = (const float*)d_in[3];
    const float* b1         = (const float*)d_in[4];
    const float* w2         = (const float*)d_in[5];
    const float* b2         = (const float*)d_in[6];
    const float* w3         = (const float*)d_in[7];
    const float* b3         = (const float*)d_in[8];
    const float* weight     = (const float*)d_in[9];
    float* out = (float*)d_out;

    float *efp, *h1p, *h2p, *obuf, *partb;
    float4* xt;
    cudaGetSymbolAddress((void**)&efp, g_efp);
    cudaGetSymbolAddress((void**)&h1p, g_h1p);
    cudaGetSymbolAddress((void**)&h2p, g_h2p);
    cudaGetSymbolAddress((void**)&obuf, g_o);
    cudaGetSymbolAddress((void**)&xt, g_xt);
    cudaGetSymbolAddress((void**)&partb, g_part);

    cudaFuncSetAttribute(conv3x3_kernel<true>,
                         cudaFuncAttributeMaxDynamicSharedMemorySize, SMEM_CONV);
    cudaFuncSetAttribute(conv3x3_kernel<false>,
                         cudaFuncAttributeMaxDynamicSharedMemorySize, SMEM_CONV);

    pad_kernel<<<(2 * 128 * HWSZ + 255) / 256, 256>>>(extra_feat, efp, 2 * 128 * HWSZ);
    transpose_x_kernel<<<(2 * 16 * HWSZ + 255) / 256, 256>>>(x, xt);

    conv3x3_kernel<true><<<dim3(16, 8, 2), 256, SMEM_CONV>>>(
        efp, w1, b1, h1p, 128, 64, PW, PW + 4, (size_t)PHW);
    conv3x3_kernel<true><<<dim3(16, 8, 2), 256, SMEM_CONV>>>(
        h1p, w2, b2, h2p, 64, 64, PW, PW + 4, (size_t)PHW);
    conv3x3_kernel<false><<<dim3(16, 54, 2), 256, SMEM_CONV>>>(
        h2p, w3, b3, obuf, 64, 432, WW, 0, (size_t)HWSZ);

    deform_kernel<<<dim3(HWSZ / 128, GSPLIT, 2), 128>>>(xt, obuf, flow, weight, partb);
    reduce_kernel<<<(2 * 64 * HWSZ / 4 + 255) / 256, 256>>>((const float4*)partb, (float4*)out);
}